// round 9
// baseline (speedup 1.0000x reference)
#include <cuda_runtime.h>

#define CIN  64
#define HH   32
#define WW   32
#define COUT 128
#define NK   9

#define XSC    307.77494205f      // PSCALE(19.235933878) * 16 idx units per b2
#define TBIAS  80.0f              // z = -5 b2  ->  index 0
#define CEXP   0.26359713812f     // 2^{-s_b2}
#define B2LIN  3.8471867757f      // 2*s_b2
#define B2SQ   3.7002114715f      // s_b2^2
#define ZTAIL  21.640425f         // 15*log2(e): exact-linear switch (b2 units)
#define OSCALE_EFF 2.7025482e-5f  // ALPHA*R*ln2^2
#define MAGIC  8388608.0f         // 2^23 round-to-nearest anchor
#define MCLAMP 8389119.0f         // MAGIC + 511

// 8192 sections = (cin, grp-of-8, co_local). Each: 9 sorted {t',pk} + INF
// sentinel packed in 5 float4. Section stride 5, bin stride 40. +8 pad.
__device__ float4 g_tab[8192 * 5 + 8];

__device__ __forceinline__ float ex2a(float x) {
    float r; asm("ex2.approx.ftz.f32 %0, %1;" : "=f"(r) : "f"(x)); return r;
}
__device__ __forceinline__ float lg2a(float x) {
    float r; asm("lg2.approx.ftz.f32 %0, %1;" : "=f"(r) : "f"(x)); return r;
}

__device__ __forceinline__ float rfun(float z) {   // r(z) in b2^2 units
    float e  = ex2a(z);
    float l1 = lg2a(1.f + e);
    float l2 = lg2a(fmaf(e, CEXP, 1.f));
    return (l1 - l2) * (l1 + l2);
}

// ---------------- prepass: per-(cin,grp,co) insertion sort of 9 ----------------
__global__ void k_sort(const float* __restrict__ theta) {
    int i = blockIdx.x * 256 + threadIdx.x;   // 8192 sections
    if (i >= 8192) return;
    int co_l = i & 7;
    int bin  = i >> 3;          // cin*16 + grp
    int grp  = bin & 15;
    int cin  = bin >> 4;
    int co   = grp * 8 + co_l;

    float th[9]; unsigned pk[9];
    #pragma unroll
    for (int kk = 0; kk < 9; ++kk) {
        th[kk] = theta[(co * CIN + cin) * NK + kk] * XSC - TBIAS;
        pk[kk] = (unsigned)(((cin & 15) * 216 + (kk / 3) * 12 + (kk % 3)) * 4);
    }
    #pragma unroll
    for (int a = 1; a < 9; ++a) {             // insertion sort ascending
        float kt = th[a]; unsigned kp = pk[a];
        int j = a - 1;
        while (j >= 0 && th[j] > kt) { th[j+1] = th[j]; pk[j+1] = pk[j]; --j; }
        th[j+1] = kt; pk[j+1] = kp;
    }
    float4* dst = g_tab + i * 5;
    #pragma unroll
    for (int k = 0; k < 4; ++k)
        dst[k] = make_float4(th[2*k], __uint_as_float(pk[2*k]),
                             th[2*k+1], __uint_as_float(pk[2*k+1]));
    dst[4] = make_float4(th[8], __uint_as_float(pk[8]),
                         __int_as_float(0x7f800000), 0.f);   // +INF sentinel
}

// ---------------- element flavors (return contribution) ----------------
__device__ __forceinline__ float pe_lut(float tp, float pv,
                                        const char* __restrict__ xc,
                                        const char* __restrict__ lutc) {
    unsigned pk = __float_as_uint(pv);
    float xp = *(const float*)(xc + (pk & 0xffffu));
    float cl = fmaxf(xp - tp, 0.f);                    // idx units; 0 <=> z=-5
    float m  = fminf(cl + MAGIC, MCLAMP);
    float fr = cl - (m - MAGIC);                       // [-.5,.5]; tail grows
    unsigned off = (__float_as_uint(m) & 0x1ffu) << 3;
    float2 lv = *(const float2*)(lutc + off);
    return fmaf(lv.y, fr, lv.x);                       // interp / exact extrap
}

__device__ __forceinline__ float pe_mufu(float tp, float pv,
                                         const char* __restrict__ xc) {
    unsigned pk = __float_as_uint(pv);
    float xp = *(const float*)(xc + (pk & 0xffffu));
    float zb = fmaf(xp - tp, 0.0625f, -5.f);           // b2 units
    float e  = ex2a(fminf(zb, ZTAIL));
    float l1 = lg2a(1.f + e);
    float l2 = lg2a(fmaf(e, CEXP, 1.f));
    float g  = (l1 - l2) * (l1 + l2);
    return (zb > ZTAIL) ? fmaf(B2LIN, zb, -B2SQ) : g;
}

template<int FLAV>
__device__ __forceinline__ float pelem(float tp, float pv,
                                       const char* __restrict__ xc,
                                       const char* __restrict__ lutc) {
    return (FLAV == 0) ? pe_mufu(tp, pv, xc) : pe_lut(tp, pv, xc, lutc);
}

// walk one co section (sorted ascending; break warp-uniform on head)
template<int FLAV>
__device__ __forceinline__ float walk1(float TH, const float4* __restrict__ p,
                                       float4 A,
                                       const char* __restrict__ xc,
                                       const char* __restrict__ lutc) {
    float acc = 0.f;
    #pragma unroll 1
    for (int k = 1; k <= 5; ++k) {
        if (A.x >= TH) break;                          // warp-uniform
        float4 A2 = __ldg(p + k);                      // prefetch (pad-safe)
        acc += pelem<FLAV>(A.x, A.y, xc, lutc);
        float r2 = pelem<FLAV>(A.z, A.w, xc, lutc);
        if (A.z < TH) acc += r2;                       // predicated select
        A = A2;
    }
    return acc;
}

template<int FLAV>
__device__ __forceinline__ void walk_bin(float TH, const float4* __restrict__ P,
                                         float* __restrict__ acc,
                                         const char* __restrict__ xc,
                                         const char* __restrict__ lutc) {
    #pragma unroll
    for (int g = 0; g < 2; ++g) {
        const float4* Q = P + g * 20;
        float4 h0 = __ldg(Q);                          // 4 heads up front: MLP
        float4 h1 = __ldg(Q + 5);
        float4 h2 = __ldg(Q + 10);
        float4 h3 = __ldg(Q + 15);
        acc[g*4+0] += walk1<FLAV>(TH, Q,      h0, xc, lutc);
        acc[g*4+1] += walk1<FLAV>(TH, Q + 5,  h1, xc, lutc);
        acc[g*4+2] += walk1<FLAV>(TH, Q + 10, h2, xc, lutc);
        acc[g*4+3] += walk1<FLAV>(TH, Q + 15, h3, xc, lutc);
    }
}

__global__ void __launch_bounds__(128, 9)
k_main(const float* __restrict__ x, float* __restrict__ out) {
    __shared__ float  s_ex[16 * 216];   // x' tile: [16 cin][18 rows][stride 12]
    __shared__ float2 s_lut[512];       // {r(z_i), central-diff slope per idx}
    __shared__ float  s_th[4 * 16];     // [warp][cin_local]: window max of x'

    const int tid  = threadIdx.x;
    const int w    = tid >> 5;
    const int lane = tid & 31;
    const int wr   = (w >> 1) * 8;
    const int wc   = (w & 1) * 4;
    const int lr   = lane >> 2;
    const int lc   = lane & 3;
    const int bt_r = (blockIdx.x >> 2) * 16;
    const int bt_c = (blockIdx.x & 3) * 8;
    const int b    = blockIdx.y;
    const int grp  = blockIdx.z;

    float acc[8];
    #pragma unroll
    for (int c = 0; c < 8; ++c) acc[c] = 0.f;

    for (int i = tid; i < 512; i += 128) {             // LUT z in [-5, 27)
        float z  = -5.f + (float)i * 0.0625f;
        float v  = rfun(z);
        float sl = (rfun(z + 0.0625f) - rfun(z - 0.0625f)) * 0.5f;
        s_lut[i] = make_float2(v, sl);
    }

    const float* xbase = x + b * (CIN * HH * WW);
    const char*  xc    = (const char*)s_ex + ((wr + lr) * 12 + wc + lc) * 4;
    const char*  lutc  = (const char*)s_lut;

    #pragma unroll 1
    for (int ph = 0; ph < 4; ++ph) {
        const int cb = ph << 4;

        __syncthreads();
        for (int idx = tid; idx < 16 * 216; idx += 128) {
            unsigned u = (unsigned)idx;
            int cl2 = u / 216u;
            int rem = u - cl2 * 216u;
            int rr  = rem / 12u;
            int cc  = rem - rr * 12u;
            int gr  = bt_r - 1 + rr;
            int gc  = bt_c - 1 + cc;
            float v = 0.f;
            if ((unsigned)gr < HH && (unsigned)gc < WW && cc < 10)
                v = xbase[(cb + cl2) * (HH * WW) + gr * WW + gc] * XSC;
            s_ex[idx] = v;
        }
        __syncthreads();

        for (int cl2 = 0; cl2 < 16; ++cl2) {           // warp window max
            const float* pw = s_ex + cl2 * 216 + wr * 12 + wc;
            float m = -1e30f;
            for (int i = lane; i < 60; i += 32) {
                int rr = i / 6, cc = i - rr * 6;
                m = fmaxf(m, pw[rr * 12 + cc]);
            }
            #pragma unroll
            for (int off = 16; off; off >>= 1)
                m = fmaxf(m, __shfl_xor_sync(0xffffffffu, m, off));
            if (lane == 0) s_th[w * 16 + cl2] = m;
        }
        __syncwarp();

        #pragma unroll 1
        for (int cl2 = 0; cl2 < 16; ++cl2) {
            const float   TH = s_th[w * 16 + cl2];
            const float4* P  = g_tab + (((cb + cl2) * 16 + grp) * 8) * 5;
            if (((cb + cl2) & 1) == 0)
                walk_bin<0>(TH, P, acc, xc, lutc);     // MUFU flavor
            else
                walk_bin<1>(TH, P, acc, xc, lutc);     // LUT flavor
        }
    }

    const int prow = bt_r + wr + lr;
    const int pcol = bt_c + wc + lc;
    float* op = out + ((long)b * COUT + grp * 8) * 1024 + prow * 32 + pcol;
    #pragma unroll
    for (int c = 0; c < 8; ++c) {
        float v = acc[c] * OSCALE_EFF;
        op[c * 1024] = fminf(fmaxf(v, 0.f), 9.f);
    }
}

extern "C" void kernel_launch(void* const* d_in, const int* in_sizes, int n_in,
                              void* d_out, int out_size) {
    const float* xin   = (const float*)d_in[0];
    const float* theta = (const float*)d_in[1];
    if (n_in >= 2 && in_sizes[0] == COUT * CIN * NK) {  // defensive swap
        const float* t = xin; xin = theta; theta = t;
    }

    k_sort<<<32, 256>>>(theta);

    dim3 grid(8, 32, 16);   // 8 spatial tiles (16x8), 32 batch, 16 co-groups of 8
    k_main<<<grid, 128>>>(xin, (float*)d_out);
}

// round 10
// speedup vs baseline: 1.3047x; 1.3047x over previous
#include <cuda_runtime.h>

#define CIN  64
#define HH   32
#define WW   32
#define COUT 128
#define NK   9

#define XSC    307.77494205f      // PSCALE(19.235933878) * 16 idx units per b2
#define TBIAS  64.0f              // z = -4 b2  ->  index 0
#define CEXP   0.26359713812f     // 2^{-s_b2}
#define ZCLMP  126.0f             // ex2 overflow guard; lg2 form exact in tail
#define OSCALE_EFF 2.7025482e-5f  // ALPHA*R*ln2^2
#define MAGIC  8388608.0f         // 2^23 round-to-nearest anchor
#define MCLAMP 8389119.0f         // MAGIC + 511

// 1024 bins = (cin, co-group-of-8). 72 sorted float2 {t'=theta*XSC-TBIAS,
// pk=(co_l<<25)|x_byte_off} ascending by theta = 36 float4. +4 global pad.
__device__ float4 g_tab[1024 * 36 + 4];

__device__ __forceinline__ float ex2a(float x) {
    float r; asm("ex2.approx.ftz.f32 %0, %1;" : "=f"(r) : "f"(x)); return r;
}
__device__ __forceinline__ float lg2a(float x) {
    float r; asm("lg2.approx.ftz.f32 %0, %1;" : "=f"(r) : "f"(x)); return r;
}

// r(z) = softplus_b2(z)^2 - softplus_b2(z-s)^2 in b2^2 units
__device__ __forceinline__ float rfun(float z) {
    float e  = ex2a(z);
    float l1 = lg2a(1.f + e);
    float l2 = lg2a(fmaf(e, CEXP, 1.f));
    return (l1 - l2) * (l1 + l2);
}

// ---------------- prepass: per-(cin, co-group-of-8) bitonic sort of 72 ----------------
__global__ void __launch_bounds__(128) k_sort(const float* __restrict__ theta) {
    __shared__ float sk[128];
    __shared__ unsigned sv[128];
    const int bx  = blockIdx.x;          // 1024 bins = cin*16 + grp
    const int cin = bx >> 4;
    const int grp = bx & 15;
    const int t   = threadIdx.x;

    float key = 1e30f;
    unsigned val = 0;
    if (t < 72) {
        int co_l = t / 9;                // 0..7
        int kk   = t - co_l * 9;
        int co   = grp * 8 + co_l;
        key = theta[(co * CIN + cin) * NK + kk] * XSC - TBIAS;
        // x byte offset in phase tile [16 cin][18 rows][12 stride]
        unsigned xoff = (unsigned)(((cin & 15) * 216 + (kk / 3) * 12 + (kk % 3)) * 4);
        val = ((unsigned)co_l << 25) | xoff;   // pk>>16 = co_l*512 = acc byte off
    }
    sk[t] = key; sv[t] = val;
    __syncthreads();

    for (int ksz = 2; ksz <= 128; ksz <<= 1) {
        for (int j = ksz >> 1; j > 0; j >>= 1) {
            int ixj = t ^ j;
            if (ixj > t) {
                bool up = ((t & ksz) == 0);
                float a = sk[t], b = sk[ixj];
                if (up ? (a > b) : (a < b)) {
                    unsigned va = sv[t], vb = sv[ixj];
                    sk[t] = b; sk[ixj] = a;
                    sv[t] = vb; sv[ixj] = va;
                }
            }
            __syncthreads();
        }
    }

    if (t < 72) {
        float2* dst = (float2*)g_tab;
        dst[bx * 72 + t] = make_float2(sk[t], __uint_as_float(sv[t]));
    }
}

// ---------------- element flavors ----------------
// LUT flavor: 0 MUFU, LUT LDS.64
__device__ __forceinline__ void pe_lut(float tp, float pv,
                                       const char* __restrict__ xc,
                                       const char* __restrict__ lutc,
                                       char* __restrict__ accc) {
    unsigned pk = __float_as_uint(pv);
    float xp = *(const float*)(xc + (pk & 0xffffu));
    float cl = fmaxf(xp - tp, 0.f);                    // idx units; 0 <=> z=-4
    float m  = fminf(cl + MAGIC, MCLAMP);
    float fr = cl - (m - MAGIC);                       // [-.5,.5]; tail grows
    unsigned off = (__float_as_uint(m) & 0x1ffu) << 3;
    float2 lv = *(const float2*)(lutc + off);
    float r  = fmaf(lv.y, fr, lv.x);                   // interp / exact extrap
    float* a = (float*)(accc + (pk >> 16));
    *a += r;
}

// MUFU flavor: 3 MUFU, select-free (lg2 form is exact in the linear tail)
__device__ __forceinline__ void pe_mufu(float tp, float pv,
                                        const char* __restrict__ xc,
                                        char* __restrict__ accc) {
    unsigned pk = __float_as_uint(pv);
    float xp = *(const float*)(xc + (pk & 0xffffu));
    float zb = fmaf(xp - tp, 0.0625f, -4.f);           // b2 units
    float e  = ex2a(fminf(zb, ZCLMP));
    float l1 = lg2a(1.f + e);
    float l2 = lg2a(fmaf(e, CEXP, 1.f));
    float r  = (l1 - l2) * (l1 + l2);
    float* a = (float*)(accc + (pk >> 16));
    *a += r;
}

__global__ void __launch_bounds__(128, 10)
k_main(const float* __restrict__ x, float* __restrict__ out) {
    __shared__ float  s_ex[16 * 216];   // x' tile: [16 cin][18 rows][stride 12]
    __shared__ float  s_acc[8 * 128];   // [8 co][128 tid]
    __shared__ float2 s_lut[512];       // {r(z_i), central-diff slope per idx}
    __shared__ float  s_th[4 * 16];     // [warp][cin_local]: window max of x'

    const int tid  = threadIdx.x;
    const int w    = tid >> 5;
    const int lane = tid & 31;
    const int wr   = (w >> 1) * 8;
    const int wc   = (w & 1) * 4;
    const int lr   = lane >> 2;
    const int lc   = lane & 3;
    const int bt_r = (blockIdx.x >> 2) * 16;
    const int bt_c = (blockIdx.x & 3) * 8;
    const int b    = blockIdx.y;
    const int grp  = blockIdx.z;

    #pragma unroll
    for (int c = 0; c < 8; ++c) s_acc[(c << 7) + tid] = 0.f;

    // LUT: 512 entries over z in [-4, 28), h = 1/16
    for (int i = tid; i < 512; i += 128) {
        float z  = -4.f + (float)i * 0.0625f;
        float v  = rfun(z);
        float sl = (rfun(z + 0.0625f) - rfun(z - 0.0625f)) * 0.5f;
        s_lut[i] = make_float2(v, sl);
    }

    const float* xbase = x + b * (CIN * HH * WW);
    const char*  xc    = (const char*)s_ex + ((wr + lr) * 12 + wc + lc) * 4;
    const char*  lutc  = (const char*)s_lut;
    char*        accc  = (char*)(s_acc + tid);

    #pragma unroll 1
    for (int ph = 0; ph < 4; ++ph) {
        const int cb = ph << 4;

        __syncthreads();
        for (int idx = tid; idx < 16 * 216; idx += 128) {
            unsigned u = (unsigned)idx;
            int cl2 = u / 216u;
            int rem = u - cl2 * 216u;
            int rr  = rem / 12u;
            int cc  = rem - rr * 12u;
            int gr  = bt_r - 1 + rr;
            int gc  = bt_c - 1 + cc;
            float v = 0.f;
            if ((unsigned)gr < HH && (unsigned)gc < WW && cc < 10)
                v = xbase[(cb + cl2) * (HH * WW) + gr * WW + gc] * XSC;
            s_ex[idx] = v;
        }
        __syncthreads();

        // per-(warp, cin) max over the warp's 10x6 window
        for (int cl2 = 0; cl2 < 16; ++cl2) {
            const float* pw = s_ex + cl2 * 216 + wr * 12 + wc;
            float m = -1e30f;
            for (int i = lane; i < 60; i += 32) {
                int rr = i / 6, cc = i - rr * 6;
                m = fmaxf(m, pw[rr * 12 + cc]);
            }
            #pragma unroll
            for (int off = 16; off; off >>= 1)
                m = fmaxf(m, __shfl_xor_sync(0xffffffffu, m, off));
            if (lane == 0) s_th[w * 16 + cl2] = m;
        }
        __syncwarp();

        // dense walk; flavor per cin: 5/8 MUFU, 3/8 LUT (pipe balancing)
        #pragma unroll 1
        for (int cl2 = 0; cl2 < 16; ++cl2) {
            const float   TH = s_th[w * 16 + cl2];
            const float4* pp = g_tab + ((cb + cl2) * 16 + grp) * 36;

            if (((cb + cl2) & 7) < 5) {
                float4 A = __ldg(pp);
                float4 B = __ldg(pp + 1);
                #pragma unroll 1
                for (int i = 0; i < 36; i += 2) {
                    if (A.x >= TH) break;            // warp-uniform
                    float4 A2 = __ldg(pp + i + 2);
                    float4 B2 = __ldg(pp + i + 3);
                    pe_mufu(A.x, A.y, xc, accc);
                    pe_mufu(A.z, A.w, xc, accc);
                    pe_mufu(B.x, B.y, xc, accc);
                    pe_mufu(B.z, B.w, xc, accc);
                    A = A2; B = B2;
                }
            } else {
                float4 A = __ldg(pp);
                float4 B = __ldg(pp + 1);
                #pragma unroll 1
                for (int i = 0; i < 36; i += 2) {
                    if (A.x >= TH) break;
                    float4 A2 = __ldg(pp + i + 2);
                    float4 B2 = __ldg(pp + i + 3);
                    pe_lut(A.x, A.y, xc, lutc, accc);
                    pe_lut(A.z, A.w, xc, lutc, accc);
                    pe_lut(B.x, B.y, xc, lutc, accc);
                    pe_lut(B.z, B.w, xc, lutc, accc);
                    A = A2; B = B2;
                }
            }
        }
    }

    // epilogue (own slots only)
    const int prow = bt_r + wr + lr;
    const int pcol = bt_c + wc + lc;
    float* op = out + ((long)b * COUT + grp * 8) * 1024 + prow * 32 + pcol;
    #pragma unroll
    for (int c = 0; c < 8; ++c) {
        float v = s_acc[(c << 7) + tid] * OSCALE_EFF;
        op[c * 1024] = fminf(fmaxf(v, 0.f), 9.f);
    }
}

extern "C" void kernel_launch(void* const* d_in, const int* in_sizes, int n_in,
                              void* d_out, int out_size) {
    const float* xin   = (const float*)d_in[0];
    const float* theta = (const float*)d_in[1];
    if (n_in >= 2 && in_sizes[0] == COUT * CIN * NK) {  // defensive swap
        const float* t = xin; xin = theta; theta = t;
    }

    k_sort<<<1024, 128>>>(theta);

    dim3 grid(8, 32, 16);   // 8 spatial tiles (16x8), 32 batch, 16 co-groups of 8
    k_main<<<grid, 128>>>(xin, (float*)d_out);
}

// round 11
// speedup vs baseline: 1.3457x; 1.0314x over previous
#include <cuda_runtime.h>

#define CIN  64
#define HH   32
#define WW   32
#define COUT 128
#define NK   9

#define PSB2   19.235933878f      // (1/(2*N_IDEAL*VT)) * log2(e): -> b2 units
#define CEXP   0.26359713812f     // 2^{-s_b2}
#define C1     0.0625f            // 1/16
#define C2     0.0164748211f      // CEXP/16
#define ZPCL   126.0f             // ex2 overflow guard (zp = z_b2 + 4)
#define OSCALE_EFF 2.7025482e-5f  // ALPHA*R*ln2^2
#define MAGIC  8388608.0f         // 2^23 round-to-nearest anchor
#define MCLAMP 8389119.0f         // MAGIC + 511

// 1024 bins = (cin, co-group-of-8). 72 sorted float2 {t'=theta_b2-4,
// pk=(co_l<<25)|x_byte_off} ascending by theta = 36 float4. +8 global pad
// (ping-pong walk prefetches up to pp+37).
__device__ float4 g_tab[1024 * 36 + 8];

__device__ __forceinline__ float ex2a(float x) {
    float r; asm("ex2.approx.ftz.f32 %0, %1;" : "=f"(r) : "f"(x)); return r;
}
__device__ __forceinline__ float lg2a(float x) {
    float r; asm("lg2.approx.ftz.f32 %0, %1;" : "=f"(r) : "f"(x)); return r;
}

// r(z) = softplus_b2(z)^2 - softplus_b2(z-s)^2 in b2^2 units (LUT build)
__device__ __forceinline__ float rfun(float z) {
    float e  = ex2a(z);
    float l1 = lg2a(1.f + e);
    float l2 = lg2a(fmaf(e, CEXP, 1.f));
    return (l1 - l2) * (l1 + l2);
}

// ---------------- prepass: per-(cin, co-group-of-8) bitonic sort of 72 ----------------
__global__ void __launch_bounds__(128) k_sort(const float* __restrict__ theta) {
    __shared__ float sk[128];
    __shared__ unsigned sv[128];
    const int bx  = blockIdx.x;          // 1024 bins = cin*16 + grp
    const int cin = bx >> 4;
    const int grp = bx & 15;
    const int t   = threadIdx.x;

    float key = 1e30f;
    unsigned val = 0;
    if (t < 72) {
        int co_l = t / 9;                // 0..7
        int kk   = t - co_l * 9;
        int co   = grp * 8 + co_l;
        key = theta[(co * CIN + cin) * NK + kk] * PSB2 - 4.0f;   // t' (b2)
        // x byte offset in phase tile [16 cin][18 rows][12 stride]
        unsigned xoff = (unsigned)(((cin & 15) * 216 + (kk / 3) * 12 + (kk % 3)) * 4);
        val = ((unsigned)co_l << 25) | xoff;   // pk>>16 = co_l*512 = acc byte off
    }
    sk[t] = key; sv[t] = val;
    __syncthreads();

    for (int ksz = 2; ksz <= 128; ksz <<= 1) {
        for (int j = ksz >> 1; j > 0; j >>= 1) {
            int ixj = t ^ j;
            if (ixj > t) {
                bool up = ((t & ksz) == 0);
                float a = sk[t], b = sk[ixj];
                if (up ? (a > b) : (a < b)) {
                    unsigned va = sv[t], vb = sv[ixj];
                    sk[t] = b; sk[ixj] = a;
                    sv[t] = vb; sv[ixj] = va;
                }
            }
            __syncthreads();
        }
    }

    if (t < 72) {
        float2* dst = (float2*)g_tab;
        dst[bx * 72 + t] = make_float2(sk[t], __uint_as_float(sv[t]));
    }
}

// ---------------- element flavors ----------------
// LUT flavor: 0 MUFU
__device__ __forceinline__ void pe_lut(float tp, float pv,
                                       const char* __restrict__ xc,
                                       const char* __restrict__ lutc,
                                       char* __restrict__ accc) {
    unsigned pk = __float_as_uint(pv);
    float xb = *(const float*)(xc + (pk & 0xffffu));   // x (b2)
    float c  = fmaxf(xb - tp, 0.f);                    // zp = z+4, lo-clamped (b2)
    float mi = fmaf(c, 16.f, MAGIC);                   // nearest-int idx anchor
    float m  = fminf(mi, MCLAMP);
    float fl = m - MAGIC;
    float fr = fmaf(c, 16.f, -fl);                     // [-.5,.5]; tail grows
    unsigned off = (__float_as_uint(m) & 0x1ffu) << 3;
    float2 lv = *(const float2*)(lutc + off);
    float r  = fmaf(lv.y, fr, lv.x);                   // interp / exact extrap
    float* a = (float*)(accc + (pk >> 16));
    *a += r;
}

// MUFU flavor: 3 MUFU, select-free; 1/16 folded into lg2 args
__device__ __forceinline__ void pe_mufu(float tp, float pv,
                                        const char* __restrict__ xc,
                                        char* __restrict__ accc) {
    unsigned pk = __float_as_uint(pv);
    float xb = *(const float*)(xc + (pk & 0xffffu));
    float zp = xb - tp;                                // z_b2 + 4
    float ep = ex2a(fminf(zp, ZPCL));                  // 2^zp
    float l1 = lg2a(fmaf(ep, C1, 1.f));                // lg2(1+2^z)
    float l2 = lg2a(fmaf(ep, C2, 1.f));                // lg2(1+2^(z-s))
    float r  = (l1 - l2) * (l1 + l2);
    float* a = (float*)(accc + (pk >> 16));
    *a += r;
}

__global__ void __launch_bounds__(128, 10)
k_main(const float* __restrict__ x, float* __restrict__ out) {
    __shared__ float  s_ex[16 * 216];   // x tile (b2): [16 cin][18 rows][12 str]
    __shared__ float  s_acc[8 * 128];   // [8 co][128 tid]
    __shared__ float2 s_lut[512];       // {r(z_i), central-diff slope per idx}
    __shared__ float  s_th[4 * 16];     // [warp][cin_local]: window max (b2)

    const int tid  = threadIdx.x;
    const int w    = tid >> 5;
    const int lane = tid & 31;
    const int wr   = (w >> 1) * 8;
    const int wc   = (w & 1) * 4;
    const int lr   = lane >> 2;
    const int lc   = lane & 3;
    const int bt_r = (blockIdx.x >> 2) * 16;
    const int bt_c = (blockIdx.x & 3) * 8;
    const int b    = blockIdx.y;
    const int grp  = blockIdx.z;

    #pragma unroll
    for (int c = 0; c < 8; ++c) s_acc[(c << 7) + tid] = 0.f;

    // LUT build: stage 514 raw values in s_ex (overwritten later by tile)
    for (int i = tid; i < 514; i += 128) {
        float z = -4.0625f + (float)i * 0.0625f;
        s_ex[i] = rfun(z);
    }
    __syncthreads();
    for (int i = tid; i < 512; i += 128)
        s_lut[i] = make_float2(s_ex[i + 1], (s_ex[i + 2] - s_ex[i]) * 0.5f);

    const float* xbase = x + b * (CIN * HH * WW);
    const char*  xc    = (const char*)s_ex + ((wr + lr) * 12 + wc + lc) * 4;
    const char*  lutc  = (const char*)s_lut;
    char*        accc  = (char*)(s_acc + tid);

    #pragma unroll 1
    for (int ph = 0; ph < 4; ++ph) {
        const int cb = ph << 4;

        __syncthreads();   // lut build done / prev phase readers done
        for (int idx = tid; idx < 16 * 216; idx += 128) {
            unsigned u = (unsigned)idx;
            int cl2 = u / 216u;
            int rem = u - cl2 * 216u;
            int rr  = rem / 12u;
            int cc  = rem - rr * 12u;
            int gr  = bt_r - 1 + rr;
            int gc  = bt_c - 1 + cc;
            float v = 0.f;
            if ((unsigned)gr < HH && (unsigned)gc < WW && cc < 10)
                v = xbase[(cb + cl2) * (HH * WW) + gr * WW + gc] * PSB2;
            s_ex[idx] = v;
        }
        __syncthreads();

        // per-(warp, cin) max over the warp's 10x6 window
        for (int cl2 = 0; cl2 < 16; ++cl2) {
            const float* pw = s_ex + cl2 * 216 + wr * 12 + wc;
            float m = -1e30f;
            for (int i = lane; i < 60; i += 32) {
                int rr = i / 6, cc = i - rr * 6;
                m = fmaxf(m, pw[rr * 12 + cc]);
            }
            #pragma unroll
            for (int off = 16; off; off >>= 1)
                m = fmaxf(m, __shfl_xor_sync(0xffffffffu, m, off));
            if (lane == 0) s_th[w * 16 + cl2] = m;
        }
        __syncwarp();

        // dense walk; flavor per cin: 5/8 MUFU, 3/8 LUT (frozen error profile)
        #pragma unroll 1
        for (int cl2 = 0; cl2 < 16; ++cl2) {
            const float   TH = s_th[w * 16 + cl2];
            const float4* pp = g_tab + ((cb + cl2) * 16 + grp) * 36;

            float4 A = __ldg(pp);
            float4 B = __ldg(pp + 1);
            if (((cb + cl2) & 7) < 5) {
                #pragma unroll 1
                for (int i = 2; i <= 36; i += 2) {     // MOV-free ping-pong
                    if (A.x >= TH) break;              // warp-uniform
                    pe_mufu(A.x, A.y, xc, accc);
                    pe_mufu(A.z, A.w, xc, accc);
                    A = __ldg(pp + i);
                    if (B.x >= TH) break;
                    pe_mufu(B.x, B.y, xc, accc);
                    pe_mufu(B.z, B.w, xc, accc);
                    B = __ldg(pp + i + 1);
                }
            } else {
                #pragma unroll 1
                for (int i = 2; i <= 36; i += 2) {
                    if (A.x >= TH) break;
                    pe_lut(A.x, A.y, xc, lutc, accc);
                    pe_lut(A.z, A.w, xc, lutc, accc);
                    A = __ldg(pp + i);
                    if (B.x >= TH) break;
                    pe_lut(B.x, B.y, xc, lutc, accc);
                    pe_lut(B.z, B.w, xc, lutc, accc);
                    B = __ldg(pp + i + 1);
                }
            }
        }
    }

    // epilogue (own slots only)
    const int prow = bt_r + wr + lr;
    const int pcol = bt_c + wc + lc;
    float* op = out + ((long)b * COUT + grp * 8) * 1024 + prow * 32 + pcol;
    #pragma unroll
    for (int c = 0; c < 8; ++c) {
        float v = s_acc[(c << 7) + tid] * OSCALE_EFF;
        op[c * 1024] = fminf(fmaxf(v, 0.f), 9.f);
    }
}

extern "C" void kernel_launch(void* const* d_in, const int* in_sizes, int n_in,
                              void* d_out, int out_size) {
    const float* xin   = (const float*)d_in[0];
    const float* theta = (const float*)d_in[1];
    if (n_in >= 2 && in_sizes[0] == COUT * CIN * NK) {  // defensive swap
        const float* t = xin; xin = theta; theta = t;
    }

    k_sort<<<1024, 128>>>(theta);

    dim3 grid(8, 32, 16);   // 8 spatial tiles (16x8), 32 batch, 16 co-groups of 8
    k_main<<<grid, 128>>>(xin, (float*)d_out);
}

// round 13
// speedup vs baseline: 1.5039x; 1.1175x over previous
#include <cuda_runtime.h>

#define CIN  64
#define HH   32
#define WW   32
#define COUT 128
#define NK   9

#define PSB2   19.235933878f      // (1/(2*N_IDEAL*VT)) * log2(e): -> b2 units
#define CEXP   0.26359713812f     // 2^{-s_b2}
#define C1     0.0625f            // 1/16
#define C2     0.0164748211f      // CEXP/16
#define ZPCL   126.0f             // ex2 overflow guard (zp = z_b2 + 4)
#define OSCALE_EFF 2.7025482e-5f  // ALPHA*R*ln2^2
#define MAGIC  8388608.0f         // 2^23 round-to-nearest anchor
#define MCLAMP 8389119.0f         // MAGIC + 511

// 1024 bins = (cin, co-group-of-8). 72 sorted float2 {t'=theta_b2-4,
// pk=(co_l<<26)|x_byte_off} ascending by theta = 36 float4. +8 pad
// (ping-pong walk prefetches up to pp+37).
__device__ float4 g_tab[1024 * 36 + 8];

__device__ __forceinline__ float ex2a(float x) {
    float r; asm("ex2.approx.ftz.f32 %0, %1;" : "=f"(r) : "f"(x)); return r;
}
__device__ __forceinline__ float lg2a(float x) {
    float r; asm("lg2.approx.ftz.f32 %0, %1;" : "=f"(r) : "f"(x)); return r;
}

// r(z) = softplus_b2(z)^2 - softplus_b2(z-s)^2 in b2^2 units (LUT build)
__device__ __forceinline__ float rfun(float z) {
    float e  = ex2a(z);
    float l1 = lg2a(1.f + e);
    float l2 = lg2a(fmaf(e, CEXP, 1.f));
    return (l1 - l2) * (l1 + l2);
}

// ---------------- prepass: per-(cin, co-group-of-8) bitonic sort of 72 ----------------
__global__ void __launch_bounds__(128) k_sort(const float* __restrict__ theta) {
    __shared__ float sk[128];
    __shared__ unsigned sv[128];
    const int bx  = blockIdx.x;          // 1024 bins = cin*16 + grp
    const int cin = bx >> 4;
    const int grp = bx & 15;
    const int t   = threadIdx.x;

    float key = 1e30f;
    unsigned val = 0;
    if (t < 72) {
        int co_l = t / 9;                // 0..7
        int kk   = t - co_l * 9;
        int co   = grp * 8 + co_l;
        key = theta[(co * CIN + cin) * NK + kk] * PSB2 - 4.0f;   // t' (b2)
        // x byte offset in phase tile [8 cin][18 rows][stride 20]
        unsigned xoff = (unsigned)((((cin & 7) * 18 + (kk / 3)) * 20 + (kk % 3)) * 4);
        val = ((unsigned)co_l << 26) | xoff;   // pk>>16 = co_l*1024 = acc byte off
    }
    sk[t] = key; sv[t] = val;
    __syncthreads();

    for (int ksz = 2; ksz <= 128; ksz <<= 1) {
        for (int j = ksz >> 1; j > 0; j >>= 1) {
            int ixj = t ^ j;
            if (ixj > t) {
                bool up = ((t & ksz) == 0);
                float a = sk[t], b = sk[ixj];
                if (up ? (a > b) : (a < b)) {
                    unsigned va = sv[t], vb = sv[ixj];
                    sk[t] = b; sk[ixj] = a;
                    sv[t] = vb; sv[ixj] = va;
                }
            }
            __syncthreads();
        }
    }

    if (t < 72) {
        float2* dst = (float2*)g_tab;
        dst[bx * 72 + t] = make_float2(sk[t], __uint_as_float(sv[t]));
    }
}

// ---------------- element flavors: one theta, two pixels ----------------
#define X2OFF 640   // +8 rows * 20 floats * 4 B: second pixel's x

// MUFU flavor: 6 MUFU / 2 px, select-free (lg2 form exact in linear tail)
__device__ __forceinline__ void pe_mufu(float tp, float pv,
                                        const char* __restrict__ xc,
                                        char* __restrict__ accc) {
    unsigned pk = __float_as_uint(pv);
    const char* xa = xc + (pk & 0xffffu);
    float x1 = *(const float*)xa;                  // x (b2), pixel 1
    float x2 = *(const float*)(xa + X2OFF);        // pixel 2 (row +8)
    float zp1 = x1 - tp, zp2 = x2 - tp;            // z_b2 + 4
    float e1 = ex2a(fminf(zp1, ZPCL));
    float e2 = ex2a(fminf(zp2, ZPCL));
    float a1 = lg2a(fmaf(e1, C1, 1.f));
    float b1 = lg2a(fmaf(e1, C2, 1.f));
    float a2 = lg2a(fmaf(e2, C1, 1.f));
    float b2 = lg2a(fmaf(e2, C2, 1.f));
    float r1 = (a1 - b1) * (a1 + b1);
    float r2 = (a2 - b2) * (a2 + b2);
    float2* acc = (float2*)(accc + (pk >> 16));
    float2 a = *acc;
    a.x += r1; a.y += r2;
    *acc = a;
}

// LUT flavor: 0 MUFU
__device__ __forceinline__ void pe_lut(float tp, float pv,
                                       const char* __restrict__ xc,
                                       const char* __restrict__ lutc,
                                       char* __restrict__ accc) {
    unsigned pk = __float_as_uint(pv);
    const char* xa = xc + (pk & 0xffffu);
    float x1 = *(const float*)xa;
    float x2 = *(const float*)(xa + X2OFF);
    float c1 = fmaxf(x1 - tp, 0.f);                // zp, lo-clamped (b2)
    float c2 = fmaxf(x2 - tp, 0.f);
    float m1 = fminf(fmaf(c1, 16.f, MAGIC), MCLAMP);
    float m2 = fminf(fmaf(c2, 16.f, MAGIC), MCLAMP);
    float f1 = fmaf(c1, 16.f, -(m1 - MAGIC));      // [-.5,.5]; tail grows
    float f2 = fmaf(c2, 16.f, -(m2 - MAGIC));
    float2 l1 = *(const float2*)(lutc + ((__float_as_uint(m1) & 0x1ffu) << 3));
    float2 l2 = *(const float2*)(lutc + ((__float_as_uint(m2) & 0x1ffu) << 3));
    float r1 = fmaf(l1.y, f1, l1.x);
    float r2 = fmaf(l2.y, f2, l2.x);
    float2* acc = (float2*)(accc + (pk >> 16));
    float2 a = *acc;
    a.x += r1; a.y += r2;
    *acc = a;
}

__global__ void __launch_bounds__(128, 9)
k_main(const float* __restrict__ x, float* __restrict__ out) {
    __shared__ float  s_ex[8 * 18 * 20];  // x tile (b2): [8 cin][18 rows][str 20]
    __shared__ float  s_acc[8 * 256];     // [8 co][128 tid * 2 px]
    __shared__ float2 s_lut[512];         // {r(z_i), central-diff slope}
    __shared__ float  s_th[4 * 8];        // [warp][cin_local]: window max (b2)

    const int tid  = threadIdx.x;
    const int w    = tid >> 5;            // warp: 4-col band
    const int lane = tid & 31;
    const int lr   = lane >> 2;           // 0..7: pixel rows lr and lr+8
    const int lc   = lane & 3;            // col within band
    const int bt_r = (blockIdx.x >> 1) * 16;   // block tile 16x16
    const int bt_c = (blockIdx.x & 1) * 16;
    const int b    = blockIdx.y;
    const int grp  = blockIdx.z;          // co group of 8

    // zero accumulators (own slots)
    #pragma unroll
    for (int c = 0; c < 8; ++c)
        ((float2*)s_acc)[c * 128 + tid] = make_float2(0.f, 0.f);

    // LUT build: stage 514 raw values in s_ex (overwritten by tile later)
    for (int i = tid; i < 514; i += 128) {
        float z = -4.0625f + (float)i * 0.0625f;
        s_ex[i] = rfun(z);
    }
    __syncthreads();
    for (int i = tid; i < 512; i += 128)
        s_lut[i] = make_float2(s_ex[i + 1], (s_ex[i + 2] - s_ex[i]) * 0.5f);

    const float* xbase = x + b * (CIN * HH * WW);
    const char*  xc    = (const char*)s_ex + (lr * 20 + w * 4 + lc) * 4;
    const char*  lutc  = (const char*)s_lut;
    char*        accc  = (char*)(s_acc + tid * 2);

    #pragma unroll 1
    for (int ph = 0; ph < 8; ++ph) {
        const int cb = ph << 3;           // 8 cin per phase

        __syncthreads();                  // lut build / prev phase readers done
        for (int idx = tid; idx < 8 * 360; idx += 128) {
            unsigned u = (unsigned)idx;
            int cl2 = u / 360u;
            int rem = u - cl2 * 360u;
            int rr  = rem / 20u;          // 0..17
            int cc  = rem - rr * 20u;     // 0..19 (18,19 pad)
            int gr  = bt_r - 1 + rr;
            int gc  = bt_c - 1 + cc;
            float v = 0.f;
            if ((unsigned)gr < HH && (unsigned)gc < WW && cc < 18)
                v = xbase[(cb + cl2) * (HH * WW) + gr * WW + gc] * PSB2;
            s_ex[idx] = v;
        }
        __syncthreads();

        // per-(warp, cin) max over the warp's 18x6 window
        for (int cl2 = 0; cl2 < 8; ++cl2) {
            const float* pw = s_ex + cl2 * 360 + w * 4;
            float m = -1e30f;
            for (int i = lane; i < 108; i += 32) {
                int rr = i / 6, cc = i - rr * 6;
                m = fmaxf(m, pw[rr * 20 + cc]);
            }
            #pragma unroll
            for (int off = 16; off; off >>= 1)
                m = fmaxf(m, __shfl_xor_sync(0xffffffffu, m, off));
            if (lane == 0) s_th[w * 8 + cl2] = m;
        }
        __syncwarp();

        // dense walk; flavor per cin: 5/8 MUFU, 3/8 LUT (frozen ratio)
        #pragma unroll 1
        for (int cl2 = 0; cl2 < 8; ++cl2) {
            const float   TH = s_th[w * 8 + cl2];
            const float4* pp = g_tab + ((cb + cl2) * 16 + grp) * 36;

            float4 A = __ldg(pp);
            float4 B = __ldg(pp + 1);
            if (((cb + cl2) & 7) < 5) {
                #pragma unroll 1
                for (int i = 2; i <= 36; i += 2) {     // MOV-free ping-pong
                    if (A.x >= TH) break;              // warp-uniform
                    pe_mufu(A.x, A.y, xc, accc);
                    pe_mufu(A.z, A.w, xc, accc);
                    A = __ldg(pp + i);
                    if (B.x >= TH) break;
                    pe_mufu(B.x, B.y, xc, accc);
                    pe_mufu(B.z, B.w, xc, accc);
                    B = __ldg(pp + i + 1);
                }
            } else {
                #pragma unroll 1
                for (int i = 2; i <= 36; i += 2) {
                    if (A.x >= TH) break;
                    pe_lut(A.x, A.y, xc, lutc, accc);
                    pe_lut(A.z, A.w, xc, lutc, accc);
                    A = __ldg(pp + i);
                    if (B.x >= TH) break;
                    pe_lut(B.x, B.y, xc, lutc, accc);
                    pe_lut(B.z, B.w, xc, lutc, accc);
                    B = __ldg(pp + i + 1);
                }
            }
        }
    }

    // epilogue: thread owns pixels (bt_r+lr, col) and (bt_r+lr+8, col), 8 co
    const int pcol = bt_c + w * 4 + lc;
    float* op = out + ((long)b * COUT + grp * 8) * 1024 + (bt_r + lr) * 32 + pcol;
    #pragma unroll
    for (int c = 0; c < 8; ++c) {
        float2 a = ((float2*)s_acc)[c * 128 + tid];
        op[c * 1024]       = fminf(fmaxf(a.x * OSCALE_EFF, 0.f), 9.f);
        op[c * 1024 + 256] = fminf(fmaxf(a.y * OSCALE_EFF, 0.f), 9.f);  // row +8
    }
}

extern "C" void kernel_launch(void* const* d_in, const int* in_sizes, int n_in,
                              void* d_out, int out_size) {
    const float* xin   = (const float*)d_in[0];
    const float* theta = (const float*)d_in[1];
    if (n_in >= 2 && in_sizes[0] == COUT * CIN * NK) {  // defensive swap
        const float* t = xin; xin = theta; theta = t;
    }

    k_sort<<<1024, 128>>>(theta);

    dim3 grid(4, 32, 16);   // 4 spatial tiles (16x16), 32 batch, 16 co-groups
    k_main<<<grid, 128>>>(xin, (float*)d_out);
}

// round 14
// speedup vs baseline: 1.5308x; 1.0179x over previous
#include <cuda_runtime.h>

#define CIN  64
#define HH   32
#define WW   32
#define COUT 128
#define NK   9

#define PSB2   19.235933878f      // (1/(2*N_IDEAL*VT)) * log2(e): -> b2 units
#define CEXP   0.26359713812f     // 2^{-s_b2}
#define C1     0.0625f            // 1/16
#define C2     0.0164748211f      // CEXP/16
#define ZPCL   126.0f             // ex2 overflow guard (zp = z_b2 + 4)
#define OSCALE_EFF 2.7025482e-5f  // ALPHA*R*ln2^2
#define MAGIC  8388608.0f         // 2^23 round-to-nearest anchor
#define MCLAMP 8389119.0f         // MAGIC + 511

// 1024 bins = (cin, co-group-of-8). 72 sorted float2 {t'=theta_b2-4,
// pk=(co_l<<27)|x_byte_off} ascending by theta = 36 float4. +8 pad
// (ping-pong walk prefetches up to pp+37).
__device__ float4 g_tab[1024 * 36 + 8];

__device__ __forceinline__ float ex2a(float x) {
    float r; asm("ex2.approx.ftz.f32 %0, %1;" : "=f"(r) : "f"(x)); return r;
}
__device__ __forceinline__ float lg2a(float x) {
    float r; asm("lg2.approx.ftz.f32 %0, %1;" : "=f"(r) : "f"(x)); return r;
}

// r(z) = softplus_b2(z)^2 - softplus_b2(z-s)^2 in b2^2 units (LUT build)
__device__ __forceinline__ float rfun(float z) {
    float e  = ex2a(z);
    float l1 = lg2a(1.f + e);
    float l2 = lg2a(fmaf(e, CEXP, 1.f));
    return (l1 - l2) * (l1 + l2);
}

// ---------------- prepass: per-(cin, co-group-of-8) bitonic sort of 72 ----------------
__global__ void __launch_bounds__(128) k_sort(const float* __restrict__ theta) {
    __shared__ float sk[128];
    __shared__ unsigned sv[128];
    const int bx  = blockIdx.x;          // 1024 bins = cin*16 + grp
    const int cin = bx >> 4;
    const int grp = bx & 15;
    const int t   = threadIdx.x;

    float key = 1e30f;
    unsigned val = 0;
    if (t < 72) {
        int co_l = t / 9;                // 0..7
        int kk   = t - co_l * 9;
        int co   = grp * 8 + co_l;
        key = theta[(co * CIN + cin) * NK + kk] * PSB2 - 4.0f;   // t' (b2)
        // x byte offset in phase tile [4 cin][18 rows][stride 36]
        unsigned xoff = (unsigned)((((cin & 3) * 18 + (kk / 3)) * 36 + (kk % 3)) * 4);
        val = ((unsigned)co_l << 27) | xoff;   // pk>>16 = co_l*2048 = acc byte off
    }
    sk[t] = key; sv[t] = val;
    __syncthreads();

    for (int ksz = 2; ksz <= 128; ksz <<= 1) {
        for (int j = ksz >> 1; j > 0; j >>= 1) {
            int ixj = t ^ j;
            if (ixj > t) {
                bool up = ((t & ksz) == 0);
                float a = sk[t], b = sk[ixj];
                if (up ? (a > b) : (a < b)) {
                    unsigned va = sv[t], vb = sv[ixj];
                    sk[t] = b; sk[ixj] = a;
                    sv[t] = vb; sv[ixj] = va;
                }
            }
            __syncthreads();
        }
    }

    if (t < 72) {
        float2* dst = (float2*)g_tab;
        dst[bx * 72 + t] = make_float2(sk[t], __uint_as_float(sv[t]));
    }
}

// ---------------- element flavors: one theta, four pixels ----------------
#define XCOFF 16     // +4 cols * 4 B
#define XROFF 1152   // +8 rows * 36 floats * 4 B

// MUFU flavor: 12 MUFU / 4 px, select-free (lg2 form exact in linear tail)
__device__ __forceinline__ void pe_mufu(float tp, float pv,
                                        const char* __restrict__ xc,
                                        char* __restrict__ accc) {
    unsigned pk = __float_as_uint(pv);
    const char* xa = xc + (pk & 0xffffu);
    float x1 = *(const float*)xa;
    float x2 = *(const float*)(xa + XCOFF);
    float x3 = *(const float*)(xa + XROFF);
    float x4 = *(const float*)(xa + XROFF + XCOFF);
    float e1 = ex2a(fminf(x1 - tp, ZPCL));
    float e2 = ex2a(fminf(x2 - tp, ZPCL));
    float e3 = ex2a(fminf(x3 - tp, ZPCL));
    float e4 = ex2a(fminf(x4 - tp, ZPCL));
    float a1 = lg2a(fmaf(e1, C1, 1.f)), b1 = lg2a(fmaf(e1, C2, 1.f));
    float a2 = lg2a(fmaf(e2, C1, 1.f)), b2 = lg2a(fmaf(e2, C2, 1.f));
    float a3 = lg2a(fmaf(e3, C1, 1.f)), b3 = lg2a(fmaf(e3, C2, 1.f));
    float a4 = lg2a(fmaf(e4, C1, 1.f)), b4 = lg2a(fmaf(e4, C2, 1.f));
    float4* acc = (float4*)(accc + (pk >> 16));
    float4 a = *acc;
    a.x += (a1 - b1) * (a1 + b1);
    a.y += (a2 - b2) * (a2 + b2);
    a.z += (a3 - b3) * (a3 + b3);
    a.w += (a4 - b4) * (a4 + b4);
    *acc = a;
}

// LUT flavor: 0 MUFU
__device__ __forceinline__ void pe_lut(float tp, float pv,
                                       const char* __restrict__ xc,
                                       const char* __restrict__ lutc,
                                       char* __restrict__ accc) {
    unsigned pk = __float_as_uint(pv);
    const char* xa = xc + (pk & 0xffffu);
    float x1 = *(const float*)xa;
    float x2 = *(const float*)(xa + XCOFF);
    float x3 = *(const float*)(xa + XROFF);
    float x4 = *(const float*)(xa + XROFF + XCOFF);
    float c1 = fmaxf(x1 - tp, 0.f);
    float c2 = fmaxf(x2 - tp, 0.f);
    float c3 = fmaxf(x3 - tp, 0.f);
    float c4 = fmaxf(x4 - tp, 0.f);
    float m1 = fminf(fmaf(c1, 16.f, MAGIC), MCLAMP);
    float m2 = fminf(fmaf(c2, 16.f, MAGIC), MCLAMP);
    float m3 = fminf(fmaf(c3, 16.f, MAGIC), MCLAMP);
    float m4 = fminf(fmaf(c4, 16.f, MAGIC), MCLAMP);
    float f1 = fmaf(c1, 16.f, -(m1 - MAGIC));
    float f2 = fmaf(c2, 16.f, -(m2 - MAGIC));
    float f3 = fmaf(c3, 16.f, -(m3 - MAGIC));
    float f4 = fmaf(c4, 16.f, -(m4 - MAGIC));
    float2 l1 = *(const float2*)(lutc + ((__float_as_uint(m1) & 0x1ffu) << 3));
    float2 l2 = *(const float2*)(lutc + ((__float_as_uint(m2) & 0x1ffu) << 3));
    float2 l3 = *(const float2*)(lutc + ((__float_as_uint(m3) & 0x1ffu) << 3));
    float2 l4 = *(const float2*)(lutc + ((__float_as_uint(m4) & 0x1ffu) << 3));
    float4* acc = (float4*)(accc + (pk >> 16));
    float4 a = *acc;
    a.x += fmaf(l1.y, f1, l1.x);
    a.y += fmaf(l2.y, f2, l2.x);
    a.z += fmaf(l3.y, f3, l3.x);
    a.w += fmaf(l4.y, f4, l4.x);
    *acc = a;
}

__global__ void __launch_bounds__(128, 7)
k_main(const float* __restrict__ x, float* __restrict__ out) {
    __shared__ float  s_ex[4 * 648];   // x tile (b2): [4 cin][18 rows][str 36]
    __shared__ float4 s_acc[8 * 128];  // [8 co][128 tid]: 4 px each
    __shared__ float2 s_lut[512];      // {r(z_i), central-diff slope}
    __shared__ float  s_th[4 * 4];     // [warp][cin_local]: window max (b2)

    const int tid  = threadIdx.x;
    const int w    = tid >> 5;         // warp: 8-col band
    const int lane = tid & 31;
    const int lr   = lane >> 2;        // rows lr, lr+8
    const int lc   = lane & 3;         // cols wc+lc, wc+lc+4
    const int wc   = w << 3;           // warp col base (0,8,16,24)
    const int bt_r = blockIdx.x << 4;  // 2 row tiles of 16; full 32-col width
    const int b    = blockIdx.y;
    const int grp  = blockIdx.z;       // co group of 8

    #pragma unroll
    for (int c = 0; c < 8; ++c)
        s_acc[c * 128 + tid] = make_float4(0.f, 0.f, 0.f, 0.f);

    // LUT build: stage 514 raw values in s_ex (overwritten by tile later)
    for (int i = tid; i < 514; i += 128) {
        float z = -4.0625f + (float)i * 0.0625f;
        s_ex[i] = rfun(z);
    }
    __syncthreads();
    for (int i = tid; i < 512; i += 128)
        s_lut[i] = make_float2(s_ex[i + 1], (s_ex[i + 2] - s_ex[i]) * 0.5f);

    const float* xbase = x + b * (CIN * HH * WW);
    const char*  xc    = (const char*)s_ex + (lr * 36 + wc + lc) * 4;
    const char*  lutc  = (const char*)s_lut;
    char*        accc  = (char*)s_acc + tid * 16;

    #pragma unroll 1
    for (int ph = 0; ph < 16; ++ph) {
        const int cb = ph << 2;        // 4 cin per phase

        __syncthreads();               // lut build / prev phase readers done
        for (int idx = tid; idx < 4 * 648; idx += 128) {
            unsigned u = (unsigned)idx;
            int cl2 = u / 648u;
            int rem = u - cl2 * 648u;
            int rr  = rem / 36u;       // 0..17
            int cc  = rem - rr * 36u;  // 0..35 (34,35 pad)
            int gr  = bt_r - 1 + rr;
            int gc  = cc - 1;
            float v = 0.f;
            if ((unsigned)gr < HH && (unsigned)gc < WW && cc < 34)
                v = xbase[(cb + cl2) * (HH * WW) + gr * WW + gc] * PSB2;
            s_ex[idx] = v;
        }
        __syncthreads();

        // per-(warp, cin) max over the warp's 18x10 window
        for (int cl2 = 0; cl2 < 4; ++cl2) {
            const float* pw = s_ex + cl2 * 648 + wc;
            float m = -1e30f;
            for (int i = lane; i < 180; i += 32) {
                int rr = i / 10, cc = i - rr * 10;
                m = fmaxf(m, pw[rr * 36 + cc]);
            }
            #pragma unroll
            for (int off = 16; off; off >>= 1)
                m = fmaxf(m, __shfl_xor_sync(0xffffffffu, m, off));
            if (lane == 0) s_th[w * 4 + cl2] = m;
        }
        __syncwarp();

        // dense walk; flavor per cin: 5/8 MUFU, 3/8 LUT (frozen map)
        #pragma unroll 1
        for (int cl2 = 0; cl2 < 4; ++cl2) {
            const float   TH = s_th[w * 4 + cl2];
            const float4* pp = g_tab + ((cb + cl2) * 16 + grp) * 36;

            float4 A = __ldg(pp);
            float4 B = __ldg(pp + 1);
            if (((cb + cl2) & 7) < 5) {
                #pragma unroll 1
                for (int i = 2; i <= 36; i += 2) {     // MOV-free ping-pong
                    if (A.x >= TH) break;              // warp-uniform
                    pe_mufu(A.x, A.y, xc, accc);
                    pe_mufu(A.z, A.w, xc, accc);
                    A = __ldg(pp + i);
                    if (B.x >= TH) break;
                    pe_mufu(B.x, B.y, xc, accc);
                    pe_mufu(B.z, B.w, xc, accc);
                    B = __ldg(pp + i + 1);
                }
            } else {
                #pragma unroll 1
                for (int i = 2; i <= 36; i += 2) {
                    if (A.x >= TH) break;
                    pe_lut(A.x, A.y, xc, lutc, accc);
                    pe_lut(A.z, A.w, xc, lutc, accc);
                    A = __ldg(pp + i);
                    if (B.x >= TH) break;
                    pe_lut(B.x, B.y, xc, lutc, accc);
                    pe_lut(B.z, B.w, xc, lutc, accc);
                    B = __ldg(pp + i + 1);
                }
            }
        }
    }

    // epilogue: thread owns (bt_r+lr / +8) x (wc+lc / +4), 8 co
    const int pcol = wc + lc;
    float* op = out + ((long)b * COUT + grp * 8) * 1024 + (bt_r + lr) * 32 + pcol;
    #pragma unroll
    for (int c = 0; c < 8; ++c) {
        float4 a = s_acc[c * 128 + tid];
        op[c * 1024]           = fminf(fmaxf(a.x * OSCALE_EFF, 0.f), 9.f);
        op[c * 1024 + 4]       = fminf(fmaxf(a.y * OSCALE_EFF, 0.f), 9.f);
        op[c * 1024 + 256]     = fminf(fmaxf(a.z * OSCALE_EFF, 0.f), 9.f);
        op[c * 1024 + 260]     = fminf(fmaxf(a.w * OSCALE_EFF, 0.f), 9.f);
    }
}

extern "C" void kernel_launch(void* const* d_in, const int* in_sizes, int n_in,
                              void* d_out, int out_size) {
    const float* xin   = (const float*)d_in[0];
    const float* theta = (const float*)d_in[1];
    if (n_in >= 2 && in_sizes[0] == COUT * CIN * NK) {  // defensive swap
        const float* t = xin; xin = theta; theta = t;
    }

    k_sort<<<1024, 128>>>(theta);

    dim3 grid(2, 32, 16);   // 2 row tiles (16x32), 32 batch, 16 co-groups of 8
    k_main<<<grid, 128>>>(xin, (float*)d_out);
}

// round 16
// speedup vs baseline: 1.5371x; 1.0041x over previous
#include <cuda_runtime.h>

#define CIN  64
#define HH   32
#define WW   32
#define COUT 128
#define NK   9

#define PSB2   19.235933878f      // (1/(2*N_IDEAL*VT)) * log2(e): -> b2 units
#define CEXP   0.26359713812f     // 2^{-s_b2}
#define C1     0.0625f            // 1/16
#define C2     0.0164748211f      // CEXP/16
#define ZPCL   126.0f             // ex2 overflow guard (zp = z_b2 + 4)
#define OSCALE_EFF 2.7025482e-5f  // ALPHA*R*ln2^2
#define MAGIC  8388608.0f         // 2^23 round-to-nearest anchor
#define MCLAMP 8389119.0f         // MAGIC + 511

typedef unsigned long long u64;

// 1024 bins = (cin, co-group-of-8). 72 sorted float2 {t'=theta_b2-4,
// pk=(co_l<<27)|x_byte_off} ascending by theta = 36 float4. +8 pad.
__device__ float4 g_tab[1024 * 36 + 8];

__device__ __forceinline__ float ex2a(float x) {
    float r; asm("ex2.approx.ftz.f32 %0, %1;" : "=f"(r) : "f"(x)); return r;
}
__device__ __forceinline__ float lg2a(float x) {
    float r; asm("lg2.approx.ftz.f32 %0, %1;" : "=f"(r) : "f"(x)); return r;
}
__device__ __forceinline__ u64 PK2(float lo, float hi) {
    u64 r; asm("mov.b64 %0, {%1, %2};" : "=l"(r) : "f"(lo), "f"(hi)); return r;
}
__device__ __forceinline__ void UPK2(float& lo, float& hi, u64 v) {
    asm("mov.b64 {%0, %1}, %2;" : "=f"(lo), "=f"(hi) : "l"(v));
}
__device__ __forceinline__ u64 ADD2(u64 a, u64 b) {
    u64 r; asm("add.rn.f32x2 %0, %1, %2;" : "=l"(r) : "l"(a), "l"(b)); return r;
}
__device__ __forceinline__ u64 MUL2(u64 a, u64 b) {
    u64 r; asm("mul.rn.f32x2 %0, %1, %2;" : "=l"(r) : "l"(a), "l"(b)); return r;
}
__device__ __forceinline__ u64 FMA2(u64 a, u64 b, u64 c) {
    u64 r; asm("fma.rn.f32x2 %0, %1, %2, %3;" : "=l"(r) : "l"(a), "l"(b), "l"(c)); return r;
}

// r(z) = softplus_b2(z)^2 - softplus_b2(z-s)^2 in b2^2 units (LUT build)
__device__ __forceinline__ float rfun(float z) {
    float e  = ex2a(z);
    float l1 = lg2a(1.f + e);
    float l2 = lg2a(fmaf(e, CEXP, 1.f));
    return (l1 - l2) * (l1 + l2);
}

// ---------------- prepass: per-(cin, co-group-of-8) bitonic sort of 72 ----------------
__global__ void __launch_bounds__(128) k_sort(const float* __restrict__ theta) {
    __shared__ float sk[128];
    __shared__ unsigned sv[128];
    const int bx  = blockIdx.x;          // 1024 bins = cin*16 + grp
    const int cin = bx >> 4;
    const int grp = bx & 15;
    const int t   = threadIdx.x;

    float key = 1e30f;
    unsigned val = 0;
    if (t < 72) {
        int co_l = t / 9;                // 0..7
        int kk   = t - co_l * 9;
        int co   = grp * 8 + co_l;
        key = theta[(co * CIN + cin) * NK + kk] * PSB2 - 4.0f;   // t' (b2)
        // x byte offset in phase tile [4 cin][18 rows][stride 36]
        unsigned xoff = (unsigned)((((cin & 3) * 18 + (kk / 3)) * 36 + (kk % 3)) * 4);
        val = ((unsigned)co_l << 27) | xoff;   // pk>>16 = co_l*2048 = acc byte off
    }
    sk[t] = key; sv[t] = val;
    __syncthreads();

    for (int ksz = 2; ksz <= 128; ksz <<= 1) {
        for (int j = ksz >> 1; j > 0; j >>= 1) {
            int ixj = t ^ j;
            if (ixj > t) {
                bool up = ((t & ksz) == 0);
                float a = sk[t], b = sk[ixj];
                if (up ? (a > b) : (a < b)) {
                    unsigned va = sv[t], vb = sv[ixj];
                    sk[t] = b; sk[ixj] = a;
                    sv[t] = vb; sv[ixj] = va;
                }
            }
            __syncthreads();
        }
    }

    if (t < 72) {
        float2* dst = (float2*)g_tab;
        dst[bx * 72 + t] = make_float2(sk[t], __uint_as_float(sv[t]));
    }
}

// ---------------- element flavors: one theta, four pixels ----------------
#define XCOFF 16     // +4 cols * 4 B
#define XROFF 1152   // +8 rows * 36 floats * 4 B

// MUFU flavor: 12 MUFU / 4 px; packed f32x2 for all post-ex2 arithmetic
__device__ __forceinline__ void pe_mufu(float tp, float pv,
                                        const char* __restrict__ xc,
                                        char* __restrict__ accc,
                                        u64 C1p, u64 C2p, u64 ONEp, u64 M1p) {
    unsigned pk = __float_as_uint(pv);
    const char* xa = xc + (pk & 0xffffu);
    float x1 = *(const float*)xa;
    float x2 = *(const float*)(xa + XCOFF);
    float x3 = *(const float*)(xa + XROFF);
    float x4 = *(const float*)(xa + XROFF + XCOFF);
    float e1 = ex2a(fminf(x1 - tp, ZPCL));
    float e2 = ex2a(fminf(x2 - tp, ZPCL));
    float e3 = ex2a(fminf(x3 - tp, ZPCL));
    float e4 = ex2a(fminf(x4 - tp, ZPCL));
    u64 ep0 = PK2(e1, e2), ep1 = PK2(e3, e4);
    u64 A0 = FMA2(ep0, C1p, ONEp), B0 = FMA2(ep0, C2p, ONEp);
    u64 A1 = FMA2(ep1, C1p, ONEp), B1 = FMA2(ep1, C2p, ONEp);
    float a1, a2, a3, a4, b1, b2, b3, b4;
    UPK2(a1, a2, A0); UPK2(a3, a4, A1);
    UPK2(b1, b2, B0); UPK2(b3, b4, B1);
    a1 = lg2a(a1); a2 = lg2a(a2); a3 = lg2a(a3); a4 = lg2a(a4);
    b1 = lg2a(b1); b2 = lg2a(b2); b3 = lg2a(b3); b4 = lg2a(b4);
    u64 ap0 = PK2(a1, a2), ap1 = PK2(a3, a4);
    u64 bp0 = PK2(b1, b2), bp1 = PK2(b3, b4);
    u64 d0 = FMA2(bp0, M1p, ap0);        // a - b
    u64 d1 = FMA2(bp1, M1p, ap1);
    u64 s0 = ADD2(ap0, bp0);             // a + b
    u64 s1 = ADD2(ap1, bp1);
    u64 r0 = MUL2(d0, s0);
    u64 r1 = MUL2(d1, s1);
    ulonglong2* acc = (ulonglong2*)(accc + (pk >> 16));
    ulonglong2 q = *acc;                 // LDS.128
    q.x = ADD2(q.x, r0);
    q.y = ADD2(q.y, r1);
    *acc = q;                            // STS.128
}

// LUT flavor: 0 MUFU; packed accumulator
__device__ __forceinline__ void pe_lut(float tp, float pv,
                                       const char* __restrict__ xc,
                                       const char* __restrict__ lutc,
                                       char* __restrict__ accc) {
    unsigned pk = __float_as_uint(pv);
    const char* xa = xc + (pk & 0xffffu);
    float x1 = *(const float*)xa;
    float x2 = *(const float*)(xa + XCOFF);
    float x3 = *(const float*)(xa + XROFF);
    float x4 = *(const float*)(xa + XROFF + XCOFF);
    float c1 = fmaxf(x1 - tp, 0.f);
    float c2 = fmaxf(x2 - tp, 0.f);
    float c3 = fmaxf(x3 - tp, 0.f);
    float c4 = fmaxf(x4 - tp, 0.f);
    float m1 = fminf(fmaf(c1, 16.f, MAGIC), MCLAMP);
    float m2 = fminf(fmaf(c2, 16.f, MAGIC), MCLAMP);
    float m3 = fminf(fmaf(c3, 16.f, MAGIC), MCLAMP);
    float m4 = fminf(fmaf(c4, 16.f, MAGIC), MCLAMP);
    float f1 = fmaf(c1, 16.f, -(m1 - MAGIC));
    float f2 = fmaf(c2, 16.f, -(m2 - MAGIC));
    float f3 = fmaf(c3, 16.f, -(m3 - MAGIC));
    float f4 = fmaf(c4, 16.f, -(m4 - MAGIC));
    float2 l1 = *(const float2*)(lutc + ((__float_as_uint(m1) & 0x1ffu) << 3));
    float2 l2 = *(const float2*)(lutc + ((__float_as_uint(m2) & 0x1ffu) << 3));
    float2 l3 = *(const float2*)(lutc + ((__float_as_uint(m3) & 0x1ffu) << 3));
    float2 l4 = *(const float2*)(lutc + ((__float_as_uint(m4) & 0x1ffu) << 3));
    float r1 = fmaf(l1.y, f1, l1.x);
    float r2 = fmaf(l2.y, f2, l2.x);
    float r3 = fmaf(l3.y, f3, l3.x);
    float r4 = fmaf(l4.y, f4, l4.x);
    ulonglong2* acc = (ulonglong2*)(accc + (pk >> 16));
    ulonglong2 q = *acc;
    q.x = ADD2(q.x, PK2(r1, r2));
    q.y = ADD2(q.y, PK2(r3, r4));
    *acc = q;
}

__global__ void __launch_bounds__(128, 7)
k_main(const float* __restrict__ x, float* __restrict__ out) {
    __shared__ float  s_ex[4 * 648];   // x tile (b2): [4 cin][18 rows][str 36]
    __shared__ float4 s_acc[8 * 128];  // [8 co][128 tid]: 4 px each
    __shared__ float2 s_lut[512];      // {r(z_i), central-diff slope}
    __shared__ float  s_th[4 * 4];     // [warp][cin_local]: window max (b2)

    const int tid  = threadIdx.x;
    const int w    = tid >> 5;         // warp: 8-col band
    const int lane = tid & 31;
    const int lr   = lane >> 2;        // rows lr, lr+8
    const int lc   = lane & 3;         // cols wc+lc, wc+lc+4
    const int wc   = w << 3;           // warp col base (0,8,16,24)
    const int bt_r = blockIdx.x << 4;  // 2 row tiles of 16; full 32-col width
    const int b    = blockIdx.y;
    const int grp  = blockIdx.z;       // co group of 8

    const u64 C1p  = PK2(C1, C1);
    const u64 C2p  = PK2(C2, C2);
    const u64 ONEp = PK2(1.f, 1.f);
    const u64 M1p  = PK2(-1.f, -1.f);

    #pragma unroll
    for (int c = 0; c < 8; ++c)
        s_acc[c * 128 + tid] = make_float4(0.f, 0.f, 0.f, 0.f);

    // LUT build: stage 514 raw values in s_ex (overwritten by tile later)
    for (int i = tid; i < 514; i += 128) {
        float z = -4.0625f + (float)i * 0.0625f;
        s_ex[i] = rfun(z);
    }
    __syncthreads();
    for (int i = tid; i < 512; i += 128)
        s_lut[i] = make_float2(s_ex[i + 1], (s_ex[i + 2] - s_ex[i]) * 0.5f);

    const float* xbase = x + b * (CIN * HH * WW);
    const char*  xc    = (const char*)s_ex + (lr * 36 + wc + lc) * 4;
    const char*  lutc  = (const char*)s_lut;
    char*        accc  = (char*)s_acc + tid * 16;

    #pragma unroll 1
    for (int ph = 0; ph < 16; ++ph) {
        const int cb = ph << 2;        // 4 cin per phase

        __syncthreads();               // lut build / prev phase readers done
        for (int idx = tid; idx < 4 * 648; idx += 128) {
            unsigned u = (unsigned)idx;
            int cl2 = u / 648u;
            int rem = u - cl2 * 648u;
            int rr  = rem / 36u;       // 0..17
            int cc  = rem - rr * 36u;  // 0..35 (34,35 pad)
            int gr  = bt_r - 1 + rr;
            int gc  = cc - 1;
            float v = 0.f;
            if ((unsigned)gr < HH && (unsigned)gc < WW && cc < 34)
                v = xbase[(cb + cl2) * (HH * WW) + gr * WW + gc] * PSB2;
            s_ex[idx] = v;
        }
        __syncthreads();

        // per-(warp, cin) max over the warp's 18x10 window
        for (int cl2 = 0; cl2 < 4; ++cl2) {
            const float* pw = s_ex + cl2 * 648 + wc;
            float m = -1e30f;
            for (int i = lane; i < 180; i += 32) {
                int rr = i / 10, cc = i - rr * 10;
                m = fmaxf(m, pw[rr * 36 + cc]);
            }
            #pragma unroll
            for (int off = 16; off; off >>= 1)
                m = fmaxf(m, __shfl_xor_sync(0xffffffffu, m, off));
            if (lane == 0) s_th[w * 4 + cl2] = m;
        }
        __syncwarp();

        // dense walk; flavor per cin: 5/8 MUFU, 3/8 LUT (frozen map)
        #pragma unroll 1
        for (int cl2 = 0; cl2 < 4; ++cl2) {
            const float   TH = s_th[w * 4 + cl2];
            const float4* pp = g_tab + ((cb + cl2) * 16 + grp) * 36;

            float4 A = __ldg(pp);
            float4 B = __ldg(pp + 1);
            if (((cb + cl2) & 7) < 5) {
                #pragma unroll 1
                for (int i = 2; i <= 36; i += 2) {     // MOV-free ping-pong
                    if (A.x >= TH) break;              // warp-uniform
                    pe_mufu(A.x, A.y, xc, accc, C1p, C2p, ONEp, M1p);
                    pe_mufu(A.z, A.w, xc, accc, C1p, C2p, ONEp, M1p);
                    A = __ldg(pp + i);
                    if (B.x >= TH) break;
                    pe_mufu(B.x, B.y, xc, accc, C1p, C2p, ONEp, M1p);
                    pe_mufu(B.z, B.w, xc, accc, C1p, C2p, ONEp, M1p);
                    B = __ldg(pp + i + 1);
                }
            } else {
                #pragma unroll 1
                for (int i = 2; i <= 36; i += 2) {
                    if (A.x >= TH) break;
                    pe_lut(A.x, A.y, xc, lutc, accc);
                    pe_lut(A.z, A.w, xc, lutc, accc);
                    A = __ldg(pp + i);
                    if (B.x >= TH) break;
                    pe_lut(B.x, B.y, xc, lutc, accc);
                    pe_lut(B.z, B.w, xc, lutc, accc);
                    B = __ldg(pp + i + 1);
                }
            }
        }
    }

    // epilogue: thread owns (bt_r+lr / +8) x (wc+lc / +4), 8 co
    const int pcol = wc + lc;
    float* op = out + ((long)b * COUT + grp * 8) * 1024 + (bt_r + lr) * 32 + pcol;
    #pragma unroll
    for (int c = 0; c < 8; ++c) {
        float4 a = s_acc[c * 128 + tid];
        op[c * 1024]       = fminf(fmaxf(a.x * OSCALE_EFF, 0.f), 9.f);
        op[c * 1024 + 4]   = fminf(fmaxf(a.y * OSCALE_EFF, 0.f), 9.f);
        op[c * 1024 + 256] = fminf(fmaxf(a.z * OSCALE_EFF, 0.f), 9.f);
        op[c * 1024 + 260] = fminf(fmaxf(a.w * OSCALE_EFF, 0.f), 9.f);
    }
}

extern "C" void kernel_launch(void* const* d_in, const int* in_sizes, int n_in,
                              void* d_out, int out_size) {
    const float* xin   = (const float*)d_in[0];
    const float* theta = (const float*)d_in[1];
    if (n_in >= 2 && in_sizes[0] == COUT * CIN * NK) {  // defensive swap
        const float* t = xin; xin = theta; theta = t;
    }

    k_sort<<<1024, 128>>>(theta);

    dim3 grid(2, 32, 16);   // 2 row tiles (16x32), 32 batch, 16 co-groups of 8
    k_main<<<grid, 128>>>(xin, (float*)d_out);
}